// round 17
// baseline (speedup 1.0000x reference)
#include <cuda_runtime.h>
#include <cuda_fp16.h>
#include <cstdint>

#define B_ 2
#define S_ 2048
#define D_ 1024
#define H_ 16
#define HD_ 64
#define M_   (B_ * S_)
#define N3_  (3 * D_)

__device__ __half g_xh[M_ * D_];
__device__ __half g_wtqh[N3_ * D_];
__device__ __half g_wtoh[D_ * D_];
__device__ __half g_valsh[M_ * D_];
__device__ __half g_qh[B_ * H_ * S_ * HD_];   // Q * 0.125*log2(e)
__device__ __half g_kh[B_ * H_ * S_ * HD_];
__device__ __half g_vh[B_ * H_ * S_ * HD_];
__device__ __half g_vth[B_ * H_ * HD_ * S_];
__device__ uint32_t g_mbits[B_ * S_ * S_ / 32];

__device__ __forceinline__ void mma_f16(float* c, const uint32_t* a, const uint32_t* b) {
    asm volatile(
        "mma.sync.aligned.m16n8k16.row.col.f32.f16.f16.f32 "
        "{%0,%1,%2,%3}, {%4,%5,%6,%7}, {%8,%9}, {%0,%1,%2,%3};"
        : "+f"(c[0]), "+f"(c[1]), "+f"(c[2]), "+f"(c[3])
        : "r"(a[0]), "r"(a[1]), "r"(a[2]), "r"(a[3]), "r"(b[0]), "r"(b[1]));
}
__device__ __forceinline__ uint32_t pack_h2(float lo, float hi) {
    __half2 h = __floats2half2_rn(lo, hi);
    return *(uint32_t*)&h;
}
__device__ __forceinline__ uint32_t smem_u32(const void* p) {
    uint32_t a;
    asm("{ .reg .u64 t; cvta.to.shared.u64 t, %1; cvt.u32.u64 %0, t; }" : "=r"(a) : "l"(p));
    return a;
}
__device__ __forceinline__ void cp16(uint32_t dst, const void* src) {
    asm volatile("cp.async.ca.shared.global [%0], [%1], 16;" :: "r"(dst), "l"(src));
}
__device__ __forceinline__ void cp_commit() {
    asm volatile("cp.async.commit_group;");
}
template <int N>
__device__ __forceinline__ void cp_wait() {
    asm volatile("cp.async.wait_group %0;" :: "n"(N));
}
__device__ __forceinline__ void ldm_x4(uint32_t* r, uint32_t addr) {
    asm volatile("ldmatrix.sync.aligned.m8n8.x4.shared.b16 {%0,%1,%2,%3}, [%4];"
                 : "=r"(r[0]), "=r"(r[1]), "=r"(r[2]), "=r"(r[3]) : "r"(addr));
}
__device__ __forceinline__ uint32_t ex2_h2(uint32_t v) {
    asm("ex2.approx.f16x2 %0, %0;" : "+r"(v));
    return v;
}
__device__ __forceinline__ uint32_t hadd2u(uint32_t a, uint32_t b) {
    uint32_t r;
    asm("add.f16x2 %0, %1, %2;" : "=r"(r) : "r"(a), "r"(b));
    return r;
}

// ---------------- fused preprocessing (unchanged) ----------------
#define PRE_BLOCKS 14336

__global__ void __launch_bounds__(256) preprocess(
    const float* __restrict__ x, const float* __restrict__ Wqkv,
    const float* __restrict__ Wo, const float* __restrict__ mask)
{
    __shared__ float t[32][33];
    const int bid = blockIdx.x, tid = threadIdx.x;

    if (bid < 2048) {
        int i = (bid * 256 + tid) * 8;
        float4 a = *(const float4*)(x + i);
        float4 b = *(const float4*)(x + i + 4);
        uint4 u;
        u.x = pack_h2(a.x, a.y); u.y = pack_h2(a.z, a.w);
        u.z = pack_h2(b.x, b.y); u.w = pack_h2(b.z, b.w);
        *(uint4*)(g_xh + i) = u;
    } else if (bid < 6144) {
        const float* src;
        __half* dst;
        int bx, by, N;
        if (bid < 5120) {
            int bb = bid - 2048;
            bx = bb % 96; by = bb / 96; N = N3_;
            src = Wqkv; dst = g_wtqh;
        } else {
            int bb = bid - 5120;
            bx = bb % 32; by = bb / 32; N = D_;
            src = Wo; dst = g_wtoh;
        }
        int n0 = bx * 32, k0 = by * 32;
        int tx = tid & 31, ty = tid >> 5;
        for (int i = ty; i < 32; i += 8)
            t[i][tx] = src[(size_t)(k0 + i) * N + n0 + tx];
        __syncthreads();
        for (int i = ty; i < 32; i += 8)
            dst[(size_t)(n0 + i) * D_ + k0 + tx] = __float2half(t[tx][i]);
    } else {
        int warp = ((bid - 6144) * 256 + tid) >> 5;
        int lane = tid & 31;
        size_t base = (size_t)warp * 128 + lane;
        float v0 = mask[base];
        float v1 = mask[base + 32];
        float v2 = mask[base + 64];
        float v3 = mask[base + 96];
        uint32_t b0 = __ballot_sync(0xffffffffu, v0 != 0.0f);
        uint32_t b1 = __ballot_sync(0xffffffffu, v1 != 0.0f);
        uint32_t b2 = __ballot_sync(0xffffffffu, v2 != 0.0f);
        uint32_t b3 = __ballot_sync(0xffffffffu, v3 != 0.0f);
        if (lane == 0) {
            uint4 u = {b0, b1, b2, b3};
            *(uint4*)&g_mbits[warp * 4] = u;
        }
    }
}

// ---------------- V -> V^T per head (unchanged) ----------------
__global__ void __launch_bounds__(256) transpose_vh()
{
    __shared__ __half tile[64][72];
    const int s0 = blockIdx.x * 64;
    const int bh = blockIdx.y;
    const int tid = threadIdx.x;
    const __half* src = g_vh + ((size_t)bh * S_ + s0) * HD_;
    __half* dst = g_vth + (size_t)bh * HD_ * S_;

#pragma unroll
    for (int i = 0; i < 2; i++) {
        int idx = tid + 256 * i;
        int r = idx >> 3, c8 = (idx & 7) * 8;
        *(uint4*)&tile[r][c8] = *(const uint4*)(src + (size_t)r * HD_ + c8);
    }
    __syncthreads();
#pragma unroll
    for (int i = 0; i < 2; i++) {
        int idx = tid + 256 * i;
        int hd = idx >> 3, cs = (idx & 7) * 8;
        __half tmp[8];
#pragma unroll
        for (int j = 0; j < 8; j++) tmp[j] = tile[cs + j][hd];
        *(uint4*)(dst + (size_t)hd * S_ + s0 + cs) = *(uint4*)tmp;
    }
}

// ---------------- fp16 mma GEMM (unchanged from R16) ----------------
#define HPITCH 36
#define HTBUF  (128 * HPITCH)
#define GSMH   (2 * 2 * HTBUF * 4)

template <int MODE>
__global__ void __launch_bounds__(256, 2) gemm_h(
    const __half* __restrict__ A, const __half* __restrict__ Bt,
    const float* __restrict__ bias, float* __restrict__ C, int N, int K)
{
    extern __shared__ uint32_t sm[];

    const int tid = threadIdx.x, wid = tid >> 5, lane = tid & 31;
    const int g = lane >> 2, t = lane & 3;
    const int wm = wid & 1, wn = wid >> 1;
    const int m0 = blockIdx.y * 128, n0 = blockIdx.x * 128;
    const int lr = tid >> 3, lc = tid & 7;

    const __half* Ag = A + (size_t)m0 * K;
    const __half* Bg = Bt + (size_t)n0 * K;

    const uint32_t sbase = smem_u32(sm);
    const uint32_t sA[2] = {sbase, sbase + 2 * HTBUF * 4};
    const uint32_t sB[2] = {sbase + HTBUF * 4, sbase + 3 * HTBUF * 4};

    const uint32_t lmo = (((lane & 7) + ((lane & 16) ? 8 : 0)) * HPITCH +
                          ((lane & 8) ? 4 : 0)) * 4;

    float acc[4][4][4];
#pragma unroll
    for (int i = 0; i < 4; i++)
#pragma unroll
        for (int j = 0; j < 4; j++)
#pragma unroll
            for (int r = 0; r < 4; r++) acc[i][j][r] = 0.0f;

    const int KT = K / 64;

#pragma unroll
    for (int i = 0; i < 4; i++) {
        int r = lr + i * 32;
        cp16(sA[0] + (r * HPITCH + lc * 4) * 4, Ag + (size_t)r * K + lc * 8);
        cp16(sB[0] + (r * HPITCH + lc * 4) * 4, Bg + (size_t)r * K + lc * 8);
    }
    cp_commit();

    for (int kb = 0; kb < KT; kb++) {
        const int cur = kb & 1;

        cp_wait<0>();
        __syncthreads();

        if (kb + 1 < KT) {
            const int nb = cur ^ 1;
            const __half* An = Ag + (size_t)(kb + 1) * 64;
            const __half* Bn = Bg + (size_t)(kb + 1) * 64;
#pragma unroll
            for (int i = 0; i < 4; i++) {
                int r = lr + i * 32;
                cp16(sA[nb] + (r * HPITCH + lc * 4) * 4, An + (size_t)r * K + lc * 8);
                cp16(sB[nb] + (r * HPITCH + lc * 4) * 4, Bn + (size_t)r * K + lc * 8);
            }
            cp_commit();
        }

        const uint32_t Ab = sA[cur] + lmo;
        const uint32_t Bb = sB[cur] + lmo;

#pragma unroll
        for (int ks = 0; ks < 4; ks++) {
            uint32_t bm[2][4];
            ldm_x4(bm[0], Bb + ((wn * 32 + 0) * HPITCH + ks * 8) * 4);
            ldm_x4(bm[1], Bb + ((wn * 32 + 16) * HPITCH + ks * 8) * 4);
#pragma unroll
            for (int mt = 0; mt < 4; mt++) {
                uint32_t a4[4];
                ldm_x4(a4, Ab + ((wm * 64 + mt * 16) * HPITCH + ks * 8) * 4);
                uint32_t af[4] = {a4[0], a4[2], a4[1], a4[3]};
                mma_f16(acc[mt][0], af, bm[0]);
                mma_f16(acc[mt][1], af, bm[0] + 2);
                mma_f16(acc[mt][2], af, bm[1]);
                mma_f16(acc[mt][3], af, bm[1] + 2);
            }
        }
    }

    if (MODE == 0) {
        const float QS = 0.125f * 1.44269504f;
#pragma unroll
        for (int nt = 0; nt < 4; nt++) {
            int col = n0 + wn * 32 + nt * 8 + 2 * t;
            int which = col >> 10;
            int d = col & 1023;
            int hh = d >> 6, hd = d & 63;
            float bx = bias[col], by = bias[col + 1];
            float sc = (which == 0) ? QS : 1.0f;
            __half* dst = (which == 0) ? g_qh : (which == 1) ? g_kh : g_vh;
#pragma unroll
            for (int mt = 0; mt < 4; mt++) {
                int m = m0 + wm * 64 + mt * 16 + g;
                int bb = m >> 11, s = m & 2047;
                size_t base = (((size_t)(bb * H_ + hh)) * S_);
                uint32_t u0 = pack_h2((acc[mt][nt][0] + bx) * sc, (acc[mt][nt][1] + by) * sc);
                uint32_t u1 = pack_h2((acc[mt][nt][2] + bx) * sc, (acc[mt][nt][3] + by) * sc);
                *(uint32_t*)&dst[(base + s) * HD_ + hd] = u0;
                *(uint32_t*)&dst[(base + s + 8) * HD_ + hd] = u1;
            }
        }
    } else {
#pragma unroll
        for (int mt = 0; mt < 4; mt++) {
            int row = m0 + wm * 64 + mt * 16 + g;
#pragma unroll
            for (int nt = 0; nt < 4; nt++) {
                int col = n0 + wn * 32 + nt * 8 + 2 * t;
                float bx = bias[col], by = bias[col + 1];
                float2 v0 = {acc[mt][nt][0] + bx, acc[mt][nt][1] + by};
                float2 v1 = {acc[mt][nt][2] + bx, acc[mt][nt][3] + by};
                *(float2*)(C + (size_t)row * N + col) = v0;
                *(float2*)(C + (size_t)(row + 8) * N + col) = v1;
            }
        }
    }
}

// ---------------- fp16 flash attention: 32 q-rows/warp (mt=2) -------------
// CTA = 128 q rows, 4 warps. 32-key subtiles keep score regs at 32.
// B-fragments (K,V) and cp.async bytes per q-row halve vs 16-row warps.
#define HP 36

__global__ void __launch_bounds__(128) attn_mma()
{
    __shared__ uint32_t Ks[2][64 * HP];
    __shared__ uint32_t Vt[2][64 * HP];

    const int q0 = blockIdx.x * 128;
    const int h = blockIdx.y, b = blockIdx.z;
    const int tid = threadIdx.x, w = tid >> 5, lane = tid & 31;
    const int g = lane >> 2, t = lane & 3;
    const int r0 = w * 32 + g;          // + mt*16, + 8
    const int bh = b * H_ + h;

    const __half* Qg = g_qh + ((size_t)bh * S_ + q0) * HD_;
    const __half* Kg = g_kh + (size_t)bh * S_ * HD_;
    const __half* Vtg = g_vth + (size_t)bh * HD_ * S_;

    uint32_t qf[2][4][4];
#pragma unroll
    for (int mt = 0; mt < 2; mt++)
#pragma unroll
        for (int ks = 0; ks < 4; ks++) {
            int c = ks * 16 + 2 * t;
            int rr = r0 + mt * 16;
            qf[mt][ks][0] = *(const uint32_t*)(Qg + (size_t)rr * HD_ + c);
            qf[mt][ks][1] = *(const uint32_t*)(Qg + (size_t)(rr + 8) * HD_ + c);
            qf[mt][ks][2] = *(const uint32_t*)(Qg + (size_t)rr * HD_ + c + 8);
            qf[mt][ks][3] = *(const uint32_t*)(Qg + (size_t)(rr + 8) * HD_ + c + 8);
        }

    float lp[2][2] = {{0.0f, 0.0f}, {0.0f, 0.0f}};
    float o[2][8][4];
#pragma unroll
    for (int mt = 0; mt < 2; mt++)
#pragma unroll
        for (int nt = 0; nt < 8; nt++)
#pragma unroll
            for (int j = 0; j < 4; j++) o[mt][nt][j] = 0.0f;

    const uint32_t* mbp[2][2];
#pragma unroll
    for (int mt = 0; mt < 2; mt++) {
        mbp[mt][0] = g_mbits + ((size_t)(b * S_ + q0 + r0 + mt * 16) * S_) / 32;
        mbp[mt][1] = mbp[mt][0] + (8 * S_) / 32;
    }

    const int lr = tid >> 3, lc = (tid & 7);
    const uint32_t ksb[2] = {smem_u32(&Ks[0][0]), smem_u32(&Ks[1][0])};
    const uint32_t vtb[2] = {smem_u32(&Vt[0][0]), smem_u32(&Vt[1][0])};

    const uint32_t lmo = (((lane & 7) + ((lane & 16) ? 8 : 0)) * HP +
                          ((lane & 8) ? 4 : 0)) * 4;

#pragma unroll
    for (int i = 0; i < 4; i++) {
        int r = lr + i * 16;
        cp16(ksb[0] + (r * HP + lc * 4) * 4, Kg + (size_t)r * HD_ + lc * 8);
        cp16(vtb[0] + (r * HP + lc * 4) * 4, Vtg + (size_t)r * S_ + lc * 8);
    }
    cp_commit();

    const int NT = S_ / 64;
    for (int it = 0; it < NT; it++) {
        const int k0 = it * 64;
        const int cur = it & 1;

        cp_wait<0>();
        __syncthreads();

        if (it + 1 < NT) {
            const int nk0 = k0 + 64, nb = cur ^ 1;
#pragma unroll
            for (int i = 0; i < 4; i++) {
                int r = lr + i * 16;
                cp16(ksb[nb] + (r * HP + lc * 4) * 4, Kg + (size_t)(nk0 + r) * HD_ + lc * 8);
                cp16(vtb[nb] + (r * HP + lc * 4) * 4, Vtg + (size_t)r * S_ + nk0 + lc * 8);
            }
            cp_commit();
        }

        uint2 wm[2][2];
#pragma unroll
        for (int mt = 0; mt < 2; mt++) {
            wm[mt][0] = *(const uint2*)(mbp[mt][0] + (k0 >> 5));
            wm[mt][1] = *(const uint2*)(mbp[mt][1] + (k0 >> 5));
        }

        const uint32_t kbase = ksb[cur] + lmo;
        const uint32_t vbase = vtb[cur] + lmo;

#pragma unroll
        for (int half = 0; half < 2; half++) {
            const int kb = half * 32;

            // GEMM1 over this 32-key subtile
            float s[2][4][4];
#pragma unroll
            for (int mt = 0; mt < 2; mt++)
#pragma unroll
                for (int nt = 0; nt < 4; nt++)
#pragma unroll
                    for (int j = 0; j < 4; j++) s[mt][nt][j] = 0.0f;
#pragma unroll
            for (int ks = 0; ks < 4; ks++) {
#pragma unroll
                for (int p = 0; p < 2; p++) {
                    uint32_t bf4[4];
                    ldm_x4(bf4, kbase + ((kb + p * 16) * HP + ks * 8) * 4);
#pragma unroll
                    for (int mt = 0; mt < 2; mt++) {
                        mma_f16(s[mt][2 * p], qf[mt][ks], bf4);
                        mma_f16(s[mt][2 * p + 1], qf[mt][ks], bf4 + 2);
                    }
                }
            }

            // mask -> pack -> ex2; l partials via HADD2
            uint32_t paf[2][4][2];
#pragma unroll
            for (int mt = 0; mt < 2; mt++) {
                uint32_t wa = half ? wm[mt][0].y : wm[mt][0].x;
                uint32_t wb = half ? wm[mt][1].y : wm[mt][1].x;
                uint32_t th0 = 0, th1 = 0;
#pragma unroll
                for (int nt = 0; nt < 4; nt++) {
                    int j0 = (nt * 8 + 2 * t) & 31;
                    float s0 = s[mt][nt][0] - (((wa >> j0) & 1) ? 1e9f : 0.0f);
                    float s1 = s[mt][nt][1] - (((wa >> (j0 + 1)) & 1) ? 1e9f : 0.0f);
                    float s2 = s[mt][nt][2] - (((wb >> j0) & 1) ? 1e9f : 0.0f);
                    float s3 = s[mt][nt][3] - (((wb >> (j0 + 1)) & 1) ? 1e9f : 0.0f);
                    paf[mt][nt][0] = ex2_h2(pack_h2(s0, s1));
                    paf[mt][nt][1] = ex2_h2(pack_h2(s2, s3));
                    th0 = hadd2u(th0, paf[mt][nt][0]);
                    th1 = hadd2u(th1, paf[mt][nt][1]);
                }
                float2 f0 = __half22float2(*(__half2*)&th0);
                float2 f1 = __half22float2(*(__half2*)&th1);
                lp[mt][0] += f0.x + f0.y;
                lp[mt][1] += f1.x + f1.y;
            }

            // GEMM2: 16-key steps within the subtile
#pragma unroll
            for (int ksl = 0; ksl < 2; ksl++) {
                uint32_t af[2][4];
#pragma unroll
                for (int mt = 0; mt < 2; mt++) {
                    af[mt][0] = paf[mt][2 * ksl][0];
                    af[mt][1] = paf[mt][2 * ksl][1];
                    af[mt][2] = paf[mt][2 * ksl + 1][0];
                    af[mt][3] = paf[mt][2 * ksl + 1][1];
                }
#pragma unroll
                for (int p = 0; p < 4; p++) {
                    uint32_t bf4[4];
                    ldm_x4(bf4, vbase + (p * 16 * HP + (kb >> 1) + ksl * 8) * 4);
#pragma unroll
                    for (int mt = 0; mt < 2; mt++) {
                        mma_f16(o[mt][2 * p], af[mt], bf4);
                        mma_f16(o[mt][2 * p + 1], af[mt], bf4 + 2);
                    }
                }
            }
        }
    }

    // epilogue
#pragma unroll
    for (int mt = 0; mt < 2; mt++) {
        float l0 = lp[mt][0], l1 = lp[mt][1];
        l0 += __shfl_xor_sync(0xffffffffu, l0, 1);
        l0 += __shfl_xor_sync(0xffffffffu, l0, 2);
        l1 += __shfl_xor_sync(0xffffffffu, l1, 1);
        l1 += __shfl_xor_sync(0xffffffffu, l1, 2);
        float i0 = 1.0f / l0, i1 = 1.0f / l1;
        int rr = q0 + r0 + mt * 16;
        __half* Og0 = g_valsh + (((size_t)h * B_ + b) * S_ + rr) * HD_;
        __half* Og1 = Og0 + 8 * HD_;
#pragma unroll
        for (int nt = 0; nt < 8; nt++) {
            *(uint32_t*)(Og0 + nt * 8 + 2 * t) = pack_h2(o[mt][nt][0] * i0, o[mt][nt][1] * i0);
            *(uint32_t*)(Og1 + nt * 8 + 2 * t) = pack_h2(o[mt][nt][2] * i1, o[mt][nt][3] * i1);
        }
    }
}

// ---------------------------------------------------------------------------
extern "C" void kernel_launch(void* const* d_in, const int* in_sizes, int n_in,
                              void* d_out, int out_size)
{
    const float* x    = (const float*)d_in[0];
    const float* mask = (const float*)d_in[1];
    const float* Wqkv = (const float*)d_in[2];
    const float* bqkv = (const float*)d_in[3];
    const float* Wo   = (const float*)d_in[4];
    const float* bo   = (const float*)d_in[5];
    float* out = (float*)d_out;

    void *p_xh, *p_wtqh, *p_wtoh, *p_valsh;
    cudaGetSymbolAddress(&p_xh, g_xh);
    cudaGetSymbolAddress(&p_wtqh, g_wtqh);
    cudaGetSymbolAddress(&p_wtoh, g_wtoh);
    cudaGetSymbolAddress(&p_valsh, g_valsh);

    cudaFuncSetAttribute(gemm_h<0>, cudaFuncAttributeMaxDynamicSharedMemorySize, GSMH);
    cudaFuncSetAttribute(gemm_h<1>, cudaFuncAttributeMaxDynamicSharedMemorySize, GSMH);

    preprocess<<<PRE_BLOCKS, 256>>>(x, Wqkv, Wo, mask);

    gemm_h<0><<<dim3(N3_ / 128, M_ / 128), 256, GSMH>>>(
        (const __half*)p_xh, (const __half*)p_wtqh, bqkv, nullptr, N3_, D_);

    transpose_vh<<<dim3(S_ / 64, B_ * H_), 256>>>();

    attn_mma<<<dim3(S_ / 128, H_, B_), 128>>>();

    gemm_h<1><<<dim3(D_ / 128, M_ / 128), 256, GSMH>>>(
        (const __half*)p_valsh, (const __half*)p_wtoh, bo, out, D_, D_);
}